// round 1
// baseline (speedup 1.0000x reference)
#include <cuda_runtime.h>
#include <math.h>

// ---------------------------------------------------------------------------
// NUFFT adjoint (Kaiser-Bessel gridding) for GB300
//   inputs : y_real (8,200000) f32, y_imag (8,200000) f32,
//            uv (200000,2) f32, weights (200000,) f32
//   output : (8,512,512) f32
//
// Pipeline: zero grid -> scatter (red.global.add.v4.f32) ->
//           IFFT over kx (strided axis, pruned output rows) ->
//           IFFT over ky + fused fftshift/crop/deapod epilogue.
// Grid layout: cell-major [kx][ky][b] float2 (batch fastest) so each tap
// updates 64 contiguous bytes -> 4x red.v4 per tap.
// ---------------------------------------------------------------------------

#define KGRID   1024
#define KLOG    10
#define NIMG    512
#define MPTS    200000
#define BATCH   8
#define JW      6
#define BETA_F  14.04f            // 2.34 * 6
#define PI_F    3.14159265358979f

#define GRID_F2 (KGRID * KGRID * BATCH)   // 8388608 float2 = 64 MB

__device__ float2 g_grid[GRID_F2];

// ---------------------------------------------------------------------------
// Kaiser-Bessel: I0 via Abramowitz & Stegun 9.8.1 / 9.8.2 (float, ~1e-7 rel)
// ---------------------------------------------------------------------------
__device__ __forceinline__ float bessel_i0(float x)
{
    if (x < 3.75f) {
        float t = x * (1.0f / 3.75f);
        t *= t;
        return 1.0f + t * (3.5156229f + t * (3.0899424f + t * (1.2067492f +
                     t * (0.2659732f + t * (0.0360768f + t * 0.0045813f)))));
    } else {
        float t = 3.75f / x;
        float p = 0.39894228f + t * (0.01328592f + t * (0.00225319f +
                  t * (-0.00157565f + t * (0.00916281f + t * (-0.02057706f +
                  t * (0.02635537f + t * (-0.01647633f + t * 0.00392377f)))))));
        return __expf(x) * rsqrtf(x) * p;
    }
}

// ---------------------------------------------------------------------------
// Zero the oversampled grid (64 MB)
// ---------------------------------------------------------------------------
__global__ void zero_kernel()
{
    float4* p = reinterpret_cast<float4*>(g_grid);
    const int n = GRID_F2 / 2;                 // 4M float4
    for (int i = blockIdx.x * blockDim.x + threadIdx.x; i < n;
         i += gridDim.x * blockDim.x)
        p[i] = make_float4(0.f, 0.f, 0.f, 0.f);
}

// ---------------------------------------------------------------------------
// Gridding scatter: one thread per measurement.
// 36 taps x 4 red.v4.f32 = 144 vector reductions per point.
// ---------------------------------------------------------------------------
__global__ __launch_bounds__(256)
void scatter_kernel(const float* __restrict__ yr, const float* __restrict__ yi,
                    const float* __restrict__ uv, const float* __restrict__ wts)
{
    int m = blockIdx.x * blockDim.x + threadIdx.x;
    if (m >= MPTS) return;

    const float2 c2 = reinterpret_cast<const float2*>(uv)[m];
    const float wt = wts[m];
    const float inv_i0b = 1.0f / bessel_i0(BETA_F);

    int ixv[JW], iyv[JW];
    float wx[JW], wy[JW];

    // axis 0 (u -> ix)
    {
        float k  = c2.x / (2.0f * PI_F) * (float)KGRID;
        float km = floorf(k - 3.0f);
        #pragma unroll
        for (int j = 0; j < JW; j++) {
            float pt = km + (float)(j + 1);
            float d  = k - pt;
            float arg = fmaxf(1.0f - d * d * (1.0f / 9.0f), 0.0f);
            wx[j] = bessel_i0(BETA_F * sqrtf(arg)) * inv_i0b;
            ixv[j] = ((int)pt + KGRID) & (KGRID - 1);
        }
    }
    // axis 1 (v -> iy)
    {
        float k  = c2.y / (2.0f * PI_F) * (float)KGRID;
        float km = floorf(k - 3.0f);
        #pragma unroll
        for (int j = 0; j < JW; j++) {
            float pt = km + (float)(j + 1);
            float d  = k - pt;
            float arg = fmaxf(1.0f - d * d * (1.0f / 9.0f), 0.0f);
            wy[j] = bessel_i0(BETA_F * sqrtf(arg)) * inv_i0b;
            iyv[j] = ((int)pt + KGRID) & (KGRID - 1);
        }
    }

    float yrw[BATCH], yiw[BATCH];
    #pragma unroll
    for (int b = 0; b < BATCH; b++) {
        yrw[b] = yr[b * MPTS + m] * wt;
        yiw[b] = yi[b * MPTS + m] * wt;
    }

    #pragma unroll
    for (int a = 0; a < JW; a++) {
        const int rowbase = ixv[a] * KGRID;
        const float wxa = wx[a];
        #pragma unroll
        for (int c = 0; c < JW; c++) {
            const float w2 = wxa * wy[c];
            float* fp = reinterpret_cast<float*>(&g_grid[(rowbase + iyv[c]) * BATCH]);
            #pragma unroll
            for (int b = 0; b < BATCH; b += 2) {
                asm volatile(
                    "red.global.add.v4.f32 [%0], {%1, %2, %3, %4};"
                    :: "l"(fp + 2 * b),
                       "f"(w2 * yrw[b]),     "f"(w2 * yiw[b]),
                       "f"(w2 * yrw[b + 1]), "f"(w2 * yiw[b + 1])
                    : "memory");
            }
        }
    }
}

// ---------------------------------------------------------------------------
// Inverse FFT helpers (unnormalized, e^{+2 pi i k n / N} -> matches ifft2*K^2)
// In-place radix-2 DIT on bit-reversed smem data, natural-order output.
// ---------------------------------------------------------------------------
#define PITCH 1025   // smem pitch in float2 (pad to break bank alignment)

__device__ __forceinline__ void init_twiddles(float2* tw, int tid)
{
    if (tid < 512) {
        float ang = (float)tid * (2.0f * PI_F / 1024.0f);
        float s, c;
        __sincosf(ang, &s, &c);
        tw[tid] = make_float2(c, s);     // +i for inverse transform
    }
}

__device__ __forceinline__ void butterfly(float2* x, const float2* tw,
                                          int bi, int s)
{
    int half = 1 << s;
    int j  = bi & (half - 1);
    int i0 = ((bi >> s) << (s + 1)) | j;
    int i1 = i0 + half;
    float2 w = tw[j << (9 - s)];
    float2 a = x[i0];
    float2 b = x[i1];
    float2 t = make_float2(b.x * w.x - b.y * w.y,
                           b.x * w.y + b.y * w.x);
    x[i0] = make_float2(a.x + t.x, a.y + t.y);
    x[i1] = make_float2(a.x - t.x, a.y - t.y);
}

// FFT along kx (the strided axis). Block = one iy pair => 16 sub-FFTs,
// 128B-contiguous global chunks (fully coalesced). Writes only x rows in
// [0,256) U [768,1024) (the rows surviving fftshift+crop).
__global__ __launch_bounds__(1024, 1)
void fft_x_kernel()
{
    extern __shared__ float2 sm[];
    float2* tw   = sm;
    float2* data = sm + 512;
    const int tid = threadIdx.x;
    init_twiddles(tw, tid);

    const int iy0 = blockIdx.x * 2;

    for (int t = tid; t < 16 * KGRID; t += 1024) {
        int ix = t >> 4;
        int c  = t & 15;                        // c = iyl*8 + b
        float2 v = g_grid[ix * (KGRID * BATCH) + (iy0 + (c >> 3)) * BATCH + (c & 7)];
        data[c * PITCH + (__brev(ix) >> 22)] = v;
    }
    __syncthreads();

    const int g = tid >> 6;        // 16 groups of 64 threads
    const int l = tid & 63;
    float2* x = data + g * PITCH;
    #pragma unroll
    for (int s = 0; s < KLOG; s++) {
        #pragma unroll
        for (int u = 0; u < 8; u++)
            butterfly(x, tw, l + (u << 6), s);
        __syncthreads();
    }

    for (int t = tid; t < 16 * 512; t += 1024) {
        int xl = t >> 4;
        int c  = t & 15;
        int xg = (xl < 256) ? xl : xl + 512;    // rows kept after shift+crop
        g_grid[xg * (KGRID * BATCH) + (iy0 + (c >> 3)) * BATCH + (c & 7)] =
            data[c * PITCH + xg];
    }
}

__device__ __forceinline__ float inv_apod(int i)
{
    float xv = ((float)i - 256.0f) * (1.0f / 1024.0f);
    float pj = PI_F * 6.0f * xv;
    float tv = BETA_F * BETA_F - pj * pj;
    float st = sqrtf(fabsf(tv));
    float num = (tv > 0.0f) ? sinhf(st) : sinf(st);
    return fmaxf(st, 1e-6f) / num;
}

// FFT along ky for the 512 surviving x rows + fused epilogue
// (fftshift, crop to 512x512, real part, de-apodization).
__global__ __launch_bounds__(1024, 1)
void fft_y_kernel(float* __restrict__ out)
{
    extern __shared__ float2 sm[];
    float2* tw   = sm;
    float2* data = sm + 512;
    const int tid = threadIdx.x;
    init_twiddles(tw, tid);

    const int x_img = blockIdx.x;
    const int x_src = (x_img + 768) & (KGRID - 1);
    const float2* row = &g_grid[x_src * (KGRID * BATCH)];

    for (int t = tid; t < BATCH * KGRID; t += 1024) {
        int iy = t >> 3;
        int b  = t & 7;
        data[b * PITCH + (__brev(iy) >> 22)] = row[t];
    }
    __syncthreads();

    const int g = tid >> 7;        // 8 groups of 128 threads
    const int l = tid & 127;
    float2* x = data + g * PITCH;
    #pragma unroll
    for (int s = 0; s < KLOG; s++) {
        #pragma unroll
        for (int u = 0; u < 4; u++)
            butterfly(x, tw, l + (u << 7), s);
        __syncthreads();
    }

    const float iax = inv_apod(x_img);
    for (int t = tid; t < BATCH * NIMG; t += 1024) {
        int b  = t >> 9;
        int yi = t & 511;
        int ys = (yi + 768) & (KGRID - 1);
        float v = data[b * PITCH + ys].x;
        out[b * (NIMG * NIMG) + x_img * NIMG + yi] = v * iax * inv_apod(yi);
    }
}

// ---------------------------------------------------------------------------
extern "C" void kernel_launch(void* const* d_in, const int* in_sizes, int n_in,
                              void* d_out, int out_size)
{
    const float* yr  = (const float*)d_in[0];
    const float* yi  = (const float*)d_in[1];
    const float* uv  = (const float*)d_in[2];
    const float* wts = (const float*)d_in[3];
    float* out = (float*)d_out;

    const int smem_f1 = (512 + 16 * PITCH) * (int)sizeof(float2);  // ~135 KB
    const int smem_f2 = (512 + 8  * PITCH) * (int)sizeof(float2);  // ~69 KB
    cudaFuncSetAttribute(fft_x_kernel,
                         cudaFuncAttributeMaxDynamicSharedMemorySize, smem_f1);
    cudaFuncSetAttribute(fft_y_kernel,
                         cudaFuncAttributeMaxDynamicSharedMemorySize, smem_f2);

    zero_kernel<<<4096, 256>>>();
    scatter_kernel<<<(MPTS + 255) / 256, 256>>>(yr, yi, uv, wts);
    fft_x_kernel<<<KGRID / 2, 1024, smem_f1>>>();
    fft_y_kernel<<<NIMG, 1024, smem_f2>>>(out);
}

// round 2
// speedup vs baseline: 1.2237x; 1.2237x over previous
#include <cuda_runtime.h>
#include <math.h>

// ---------------------------------------------------------------------------
// NUFFT adjoint (Kaiser-Bessel gridding) for GB300 — round 2
//   zero grid -> scatter (red.global.add.v4.f32) ->
//   radix-4 IFFT over kx (pruned output rows) ->
//   radix-4 IFFT over ky + fused fftshift/crop/deapod epilogue.
// Grid layout: cell-major [kx][ky][b] float2 (batch fastest).
// FFT: 1024-pt radix-4 DIT in smem, digit-reversed load, conflict-free
// dual thread mapping (fft-major for stages 0-1, element-major for 2-4).
// ---------------------------------------------------------------------------

#define KGRID   1024
#define NIMG    512
#define MPTS    200000
#define BATCH   8
#define JW      6
#define BETA_F  14.04f            // 2.34 * 6
#define PI_F    3.14159265358979f

#define GRID_F2 (KGRID * KGRID * BATCH)   // 8388608 float2 = 64 MB
#define PITCH   1025                      // smem row pitch in float2

__device__ float2 g_grid[GRID_F2];

// ---------------------------------------------------------------------------
__device__ __forceinline__ float bessel_i0(float x)
{
    if (x < 3.75f) {
        float t = x * (1.0f / 3.75f);
        t *= t;
        return 1.0f + t * (3.5156229f + t * (3.0899424f + t * (1.2067492f +
                     t * (0.2659732f + t * (0.0360768f + t * 0.0045813f)))));
    } else {
        float t = 3.75f / x;
        float p = 0.39894228f + t * (0.01328592f + t * (0.00225319f +
                  t * (-0.00157565f + t * (0.00916281f + t * (-0.02057706f +
                  t * (0.02635537f + t * (-0.01647633f + t * 0.00392377f)))))));
        return __expf(x) * rsqrtf(x) * p;
    }
}

// ---------------------------------------------------------------------------
__global__ void zero_kernel()
{
    float4* p = reinterpret_cast<float4*>(g_grid);
    const int n = GRID_F2 / 2;
    for (int i = blockIdx.x * blockDim.x + threadIdx.x; i < n;
         i += gridDim.x * blockDim.x)
        p[i] = make_float4(0.f, 0.f, 0.f, 0.f);
}

// ---------------------------------------------------------------------------
__global__ __launch_bounds__(256)
void scatter_kernel(const float* __restrict__ yr, const float* __restrict__ yi,
                    const float* __restrict__ uv, const float* __restrict__ wts)
{
    int m = blockIdx.x * blockDim.x + threadIdx.x;
    if (m >= MPTS) return;

    const float2 c2 = reinterpret_cast<const float2*>(uv)[m];
    const float wt = wts[m];
    const float inv_i0b = 1.0f / bessel_i0(BETA_F);

    int ixv[JW], iyv[JW];
    float wx[JW], wy[JW];

    {
        float k  = c2.x / (2.0f * PI_F) * (float)KGRID;
        float km = floorf(k - 3.0f);
        #pragma unroll
        for (int j = 0; j < JW; j++) {
            float pt = km + (float)(j + 1);
            float d  = k - pt;
            float arg = fmaxf(1.0f - d * d * (1.0f / 9.0f), 0.0f);
            wx[j] = bessel_i0(BETA_F * sqrtf(arg)) * inv_i0b;
            ixv[j] = ((int)pt + KGRID) & (KGRID - 1);
        }
    }
    {
        float k  = c2.y / (2.0f * PI_F) * (float)KGRID;
        float km = floorf(k - 3.0f);
        #pragma unroll
        for (int j = 0; j < JW; j++) {
            float pt = km + (float)(j + 1);
            float d  = k - pt;
            float arg = fmaxf(1.0f - d * d * (1.0f / 9.0f), 0.0f);
            wy[j] = bessel_i0(BETA_F * sqrtf(arg)) * inv_i0b;
            iyv[j] = ((int)pt + KGRID) & (KGRID - 1);
        }
    }

    float yrw[BATCH], yiw[BATCH];
    #pragma unroll
    for (int b = 0; b < BATCH; b++) {
        yrw[b] = yr[b * MPTS + m] * wt;
        yiw[b] = yi[b * MPTS + m] * wt;
    }

    #pragma unroll
    for (int a = 0; a < JW; a++) {
        const int rowbase = ixv[a] * KGRID;
        const float wxa = wx[a];
        #pragma unroll
        for (int c = 0; c < JW; c++) {
            const float w2 = wxa * wy[c];
            float* fp = reinterpret_cast<float*>(&g_grid[(rowbase + iyv[c]) * BATCH]);
            #pragma unroll
            for (int b = 0; b < BATCH; b += 2) {
                asm volatile(
                    "red.global.add.v4.f32 [%0], {%1, %2, %3, %4};"
                    :: "l"(fp + 2 * b),
                       "f"(w2 * yrw[b]),     "f"(w2 * yiw[b]),
                       "f"(w2 * yrw[b + 1]), "f"(w2 * yiw[b + 1])
                    : "memory");
            }
        }
    }
}

// ---------------------------------------------------------------------------
// Radix-4 helpers
// ---------------------------------------------------------------------------
__device__ __forceinline__ int digit_rev10(int i)
{
    int r = (int)(__brev((unsigned)i) >> 22);               // bit-reverse 10b
    return ((r & 0x155) << 1) | ((r & 0x2AA) >> 1);         // swap bit pairs
}

__device__ __forceinline__ float2 cmul(float2 a, float2 b)
{
    return make_float2(a.x * b.x - a.y * b.y, a.x * b.y + a.y * b.x);
}

// inverse-FFT radix-4 butterfly (twiddle table holds e^{+i 2 pi k / 1024})
__device__ __forceinline__ void bf4(float2* x, const float2* tw, int bi, int s)
{
    const int sh = 2 * s;
    const int quarter = 1 << sh;
    const int j = bi & (quarter - 1);
    const int base = ((bi >> sh) << (sh + 2)) | j;

    float2 b0 = x[base];
    float2 b1 = x[base + quarter];
    float2 b2 = x[base + 2 * quarter];
    float2 b3 = x[base + 3 * quarter];
    if (s > 0) {
        const int e = j << (8 - sh);     // j * 256 / quarter  (< 256)
        b1 = cmul(b1, tw[e]);
        b2 = cmul(b2, tw[2 * e]);
        b3 = cmul(b3, tw[3 * e]);
    }
    float2 t0 = make_float2(b0.x + b2.x, b0.y + b2.y);
    float2 t1 = make_float2(b0.x - b2.x, b0.y - b2.y);
    float2 t2 = make_float2(b1.x + b3.x, b1.y + b3.y);
    float2 t3 = make_float2(-(b1.y - b3.y), b1.x - b3.x);   // +i*(b1-b3)
    x[base]               = make_float2(t0.x + t2.x, t0.y + t2.y);
    x[base + quarter]     = make_float2(t1.x + t3.x, t1.y + t3.y);
    x[base + 2 * quarter] = make_float2(t0.x - t2.x, t0.y - t2.y);
    x[base + 3 * quarter] = make_float2(t1.x - t3.x, t1.y - t3.y);
}

// 16 independent 1024-pt FFTs in smem rows; 1024 threads.
// Stages 0-1: fft-major mapping (conflict-free via pitch), 2-4: element-major.
__device__ __forceinline__ void fft16x1024(float2* data, const float2* tw,
                                           int tid)
{
    #pragma unroll
    for (int s = 0; s < 5; s++) {
        float2* x;
        int bi0;
        if (s < 2) { x = data + (tid & 15) * PITCH;  bi0 = tid >> 4; }
        else       { x = data + (tid >> 6) * PITCH;  bi0 = tid & 63; }
        #pragma unroll
        for (int u = 0; u < 4; u++)
            bf4(x, tw, bi0 + (u << 6), s);
        __syncthreads();
    }
}

__device__ __forceinline__ void init_tw(float2* tw, int tid)
{
    if (tid < 768) {
        float ang = (float)tid * (2.0f * PI_F / 1024.0f);
        float s, c;
        __sincosf(ang, &s, &c);
        tw[tid] = make_float2(c, s);
    }
}

// ---------------------------------------------------------------------------
// FFT along kx. Block = iy pair -> 16 (iy,b) columns. Pruned output rows.
// ---------------------------------------------------------------------------
__global__ __launch_bounds__(1024, 1)
void fft_x_kernel()
{
    extern __shared__ float2 sm[];
    float2* tw   = sm;
    float2* data = sm + 768;
    const int tid = threadIdx.x;
    init_tw(tw, tid);

    const int iy0 = blockIdx.x * 2;

    for (int t = tid; t < 16 * KGRID; t += 1024) {
        int ix = t >> 4;
        int c  = t & 15;                        // c = iyl*8 + b
        float2 v = g_grid[ix * (KGRID * BATCH) + (iy0 + (c >> 3)) * BATCH + (c & 7)];
        data[c * PITCH + digit_rev10(ix)] = v;
    }
    __syncthreads();

    fft16x1024(data, tw, tid);

    for (int t = tid; t < 16 * 512; t += 1024) {
        int xl = t >> 4;
        int c  = t & 15;
        int xg = (xl < 256) ? xl : xl + 512;    // rows kept after shift+crop
        g_grid[xg * (KGRID * BATCH) + (iy0 + (c >> 3)) * BATCH + (c & 7)] =
            data[c * PITCH + xg];
    }
}

// ---------------------------------------------------------------------------
__device__ __forceinline__ float inv_apod(int i)
{
    float xv = ((float)i - 256.0f) * (1.0f / 1024.0f);
    float pj = PI_F * 6.0f * xv;
    float tv = BETA_F * BETA_F - pj * pj;
    float st = sqrtf(fabsf(tv));
    float num = (tv > 0.0f) ? sinhf(st) : sinf(st);
    return fmaxf(st, 1e-6f) / num;
}

// FFT along ky for 2 surviving x rows (16 (row,b) FFTs) + fused epilogue.
__global__ __launch_bounds__(1024, 1)
void fft_y_kernel(float* __restrict__ out)
{
    extern __shared__ float2 sm[];
    float2* tw   = sm;
    float2* data = sm + 768;
    const int tid = threadIdx.x;
    init_tw(tw, tid);

    const int x_img0 = blockIdx.x * 2;

    for (int t = tid; t < 16 * KGRID; t += 1024) {
        int iy = t >> 4;
        int c  = t & 15;                        // c = xl*8 + b
        int x_src = ((x_img0 + (c >> 3)) + 768) & (KGRID - 1);
        float2 v = g_grid[x_src * (KGRID * BATCH) + iy * BATCH + (c & 7)];
        data[c * PITCH + digit_rev10(iy)] = v;
    }
    __syncthreads();

    fft16x1024(data, tw, tid);

    const float iax0 = inv_apod(x_img0);
    const float iax1 = inv_apod(x_img0 + 1);
    for (int t = tid; t < 16 * NIMG; t += 1024) {
        int c  = t >> 9;                        // c = b*2 + xl
        int yi = t & 511;
        int b  = c >> 1;
        int xl = c & 1;
        int ys = (yi + 768) & (KGRID - 1);
        float v = data[((xl << 3) | b) * PITCH + ys].x;
        out[b * (NIMG * NIMG) + (x_img0 + xl) * NIMG + yi] =
            v * (xl ? iax1 : iax0) * inv_apod(yi);
    }
}

// ---------------------------------------------------------------------------
extern "C" void kernel_launch(void* const* d_in, const int* in_sizes, int n_in,
                              void* d_out, int out_size)
{
    const float* yr  = (const float*)d_in[0];
    const float* yi  = (const float*)d_in[1];
    const float* uv  = (const float*)d_in[2];
    const float* wts = (const float*)d_in[3];
    float* out = (float*)d_out;

    const int smem_fft = (768 + 16 * PITCH) * (int)sizeof(float2);  // ~134 KB
    cudaFuncSetAttribute(fft_x_kernel,
                         cudaFuncAttributeMaxDynamicSharedMemorySize, smem_fft);
    cudaFuncSetAttribute(fft_y_kernel,
                         cudaFuncAttributeMaxDynamicSharedMemorySize, smem_fft);

    zero_kernel<<<4096, 256>>>();
    scatter_kernel<<<(MPTS + 255) / 256, 256>>>(yr, yi, uv, wts);
    fft_x_kernel<<<KGRID / 2, 1024, smem_fft>>>();
    fft_y_kernel<<<NIMG / 2, 1024, smem_fft>>>(out);
}